// round 12
// baseline (speedup 1.0000x reference)
#include <cuda_runtime.h>
#include <math.h>

#define N_NODES 50000
#define N_EDGES 600000
#define N_RELS  500
#define DIM     128
#define NODE_BLOCKS ((N_NODES + 63) / 64)   // 782
#define REL_BLOCKS  ((N_RELS + 63) / 64)    // 8
#define SCAN_CHUNKS ((N_NODES + 255) / 256)   // 196
#define SCAN_FLAG   (1ull << 63)

// ---- scratch (no allocations allowed) ----
__device__ __align__(16) float g_m_node[N_NODES * DIM];
__device__ __align__(16) float g_m_rel[N_RELS * DIM];
__device__ float g_s_src[N_NODES];
__device__ float g_s_tgt[N_NODES];
__device__ float g_s_rel[N_RELS];
__device__ float g_dummy[N_RELS];
__device__ int   g_count[N_NODES];       // zero-init; re-zeroed by scan phase each run
__device__ int   g_offset[N_NODES + 1];
__device__ int   g_cursor[N_NODES];
__device__ unsigned long long g_scan_ll[SCAN_CHUNKS];  // aggregate | FLAG; reset by k_precomp
__device__ __align__(8) uint2 g_epack[N_EDGES];   // {src | rel<<16, exp(score) bits}

// software grid barrier state (phase is monotonic across graph replays)
__device__ unsigned g_bar_count = 0;
__device__ unsigned g_bar_phase = 0;

// ---------------------------------------------------------------------------
__device__ __forceinline__ unsigned long long fma2(unsigned long long a,
                                                   unsigned long long b,
                                                   unsigned long long c) {
    unsigned long long d;
    asm("fma.rn.f32x2 %0, %1, %2, %3;" : "=l"(d) : "l"(a), "l"(b), "l"(c));
    return d;
}
__device__ __forceinline__ unsigned long long pack2(float x) {
    unsigned long long d;
    asm("mov.b64 %0, {%1, %1};" : "=l"(d) : "r"(__float_as_uint(x)));
    return d;
}
union F4U { float4 f4; unsigned long long u[2]; };

__device__ __forceinline__ void grid_barrier(unsigned nblocks) {
    __syncthreads();
    if (threadIdx.x == 0) {
        unsigned old_phase = atomicAdd(&g_bar_phase, 0u);
        __threadfence();
        unsigned arrived = atomicAdd(&g_bar_count, 1u);
        if (arrived == nblocks - 1) {
            atomicExch(&g_bar_count, 0u);
            __threadfence();
            atomicAdd(&g_bar_phase, 1u);
        } else {
            while (atomicAdd(&g_bar_phase, 0u) == old_phase) {}
        }
        __threadfence();
    }
    __syncthreads();
}

// ---------------------------------------------------------------------------
// Merged row transform for nodes AND rels in one launch (proven R8-R11 form).
__global__ void k_precomp(const float* __restrict__ Xn, const float* __restrict__ Xr,
                          const float* __restrict__ Wn, const float* __restrict__ bn,
                          const float* __restrict__ Wr, const float* __restrict__ br,
                          const float* __restrict__ attn_w,
                          const int4* __restrict__ dst4) {
    extern __shared__ float sm[];
    float* Wt  = sm;                    // 128*132
    float* xs  = Wt + DIM * 132;        // 64*128
    float* sv1 = xs + 64 * DIM;         // 128
    float* sv2 = sv1 + DIM;             // 128

    int tid = threadIdx.x;
    int blk = blockIdx.x;
    int mode = (blk >= NODE_BLOCKS);

    // reset scan flags for this execution (196 < 256)
    if (blk == 0 && tid < SCAN_CHUNKS) g_scan_ll[tid] = 0ull;

    const float* X  = mode ? Xr : Xn;
    const float* W  = mode ? Wr : Wn;
    const float* b  = mode ? br : bn;
    const float* v1 = mode ? attn_w + 2 * DIM : attn_w;
    const float* v2 = mode ? attn_w + 2 * DIM : attn_w + DIM;
    float* out_m  = mode ? g_m_rel : g_m_node;
    float* out_s1 = mode ? g_s_rel : g_s_src;
    float* out_s2 = mode ? g_dummy : g_s_tgt;
    int n_rows    = mode ? N_RELS  : N_NODES;
    int base      = (mode ? (blk - NODE_BLOCKS) : blk) * 64;

    // fused histogram over all blocks
    for (int i = blk * blockDim.x + tid; i < N_EDGES / 4; i += gridDim.x * blockDim.x) {
        int4 d = dst4[i];
        atomicAdd(&g_count[d.x], 1);
        atomicAdd(&g_count[d.y], 1);
        atomicAdd(&g_count[d.z], 1);
        atomicAdd(&g_count[d.w], 1);
    }

    for (int idx = tid; idx < DIM * DIM; idx += blockDim.x) {
        int j = idx >> 7, k = idx & 127;
        Wt[k * 132 + j] = W[idx];
    }
    for (int k = tid; k < DIM; k += blockDim.x) { sv1[k] = v1[k]; sv2[k] = v2[k]; }

    for (int idx = tid; idx < 64 * (DIM / 4); idx += blockDim.x) {
        int n = idx >> 5, c = idx & 31;
        int row = base + n;
        float4 v = make_float4(0.f, 0.f, 0.f, 0.f);
        if (row < n_rows) v = ((const float4*)X)[row * (DIM / 4) + c];
        ((float4*)xs)[n * (DIM / 4) + c] = v;
    }
    __syncthreads();

    int warp = tid >> 5, lane = tid & 31;
    F4U bu; bu.f4 = ((const float4*)b)[lane];

    unsigned long long alo[8], ahi[8];
#pragma unroll
    for (int i = 0; i < 8; i++) { alo[i] = bu.u[0]; ahi[i] = bu.u[1]; }

    int n0 = warp * 8;
    const float4* xr4 = (const float4*)(xs + n0 * DIM);   // row stride 32 float4
    const float4* Wt4 = (const float4*)Wt;                // row stride 33 float4

#pragma unroll 2
    for (int k4 = 0; k4 < DIM / 4; k4++) {
        float4 xv[8];
#pragma unroll
        for (int i = 0; i < 8; i++) xv[i] = xr4[i * 32 + k4];
#pragma unroll
        for (int q = 0; q < 4; q++) {
            int k = k4 * 4 + q;
            F4U w; w.f4 = Wt4[k * 33 + lane];
#pragma unroll
            for (int i = 0; i < 8; i++) {
                float xc = (q == 0) ? xv[i].x : (q == 1) ? xv[i].y
                         : (q == 2) ? xv[i].z : xv[i].w;
                unsigned long long xx = pack2(xc);
                alo[i] = fma2(w.u[0], xx, alo[i]);
                ahi[i] = fma2(w.u[1], xx, ahi[i]);
            }
        }
    }

    const float* xr0 = xs + n0 * DIM;
#pragma unroll
    for (int i = 0; i < 8; i++) {
        int row = base + n0 + i;
        if (row >= n_rows) break;
        F4U o; o.u[0] = alo[i]; o.u[1] = ahi[i];
        ((float4*)out_m)[row * (DIM / 4) + lane] = o.f4;
        const float* xr = xr0 + i * DIM;
        float p1 = 0.f, p2 = 0.f;
#pragma unroll
        for (int q = 0; q < 4; q++) {
            int k = lane * 4 + q;
            float xv = xr[k];
            p1 += xv * sv1[k];
            p2 += xv * sv2[k];
        }
#pragma unroll
        for (int o2 = 16; o2; o2 >>= 1) {
            p1 += __shfl_down_sync(0xffffffffu, p1, o2);
            p2 += __shfl_down_sync(0xffffffffu, p2, o2);
        }
        if (lane == 0) { out_s1[row] = p1; out_s2[row] = p2; }
    }
}

// ---------------------------------------------------------------------------
// Persistent fused kernel: Phase A = lookback scan, Phase B = CSR fill,
// Phase C = warp-per-node aggregate. Two software grid barriers between.
// Grid sized by occupancy (co-residency guaranteed by the host launcher).
__global__ void __launch_bounds__(256, 4)
k_fused(const int4* __restrict__ src4, const int4* __restrict__ dst4,
        const int4* __restrict__ rel4, const float* __restrict__ attn_b,
        const float* __restrict__ node_emb, float* __restrict__ out,
        unsigned nblocks) {
    int tid = threadIdx.x;
    int blk = blockIdx.x;

    // ---- Phase A: decoupled-lookback exclusive scan (proven R11 form) ----
    if (blk < SCAN_CHUNKS) {
        __shared__ int s[256];
        __shared__ int s_carry;
        int idx = blk * 256 + tid;
        int v = (idx < N_NODES) ? g_count[idx] : 0;
        s[tid] = v;
        __syncthreads();
#pragma unroll
        for (int off = 1; off < 256; off <<= 1) {
            int t = (tid >= off) ? s[tid - off] : 0;
            __syncthreads();
            s[tid] += t;
            __syncthreads();
        }
        int incl = s[tid];

        if (tid == 255)
            atomicExch(&g_scan_ll[blk], (unsigned long long)(unsigned)s[255] | SCAN_FLAG);

        if (tid < 32) {
            int running = 0;
            int pos = blk - 1 - tid;
            while (__any_sync(0xffffffffu, pos >= 0)) {
                if (pos >= 0) {
                    unsigned long long got;
                    do { got = atomicAdd(&g_scan_ll[pos], 0ull); } while (!(got & SCAN_FLAG));
                    running += (int)(unsigned)(got & 0xFFFFFFFFull);
                }
                pos -= 32;
            }
#pragma unroll
            for (int o = 16; o; o >>= 1) running += __shfl_xor_sync(0xffffffffu, running, o);
            if (tid == 0) s_carry = running;
        }
        __syncthreads();
        int carry = s_carry;

        if (idx < N_NODES) {
            int o = carry + incl - v;
            g_offset[idx] = o;
            g_cursor[idx] = o;
            g_count[idx]  = 0;
        }
        if (idx == 0) g_offset[N_NODES] = N_EDGES;
    }

    grid_barrier(nblocks);

    // ---- Phase B: CSR fill with precomputed exp (proven R8 form) ----
    {
        float ab = attn_b[0];
        for (int i = blk * 256 + tid; i < N_EDGES / 4; i += nblocks * 256) {
            int4 s = src4[i];
            int4 d = dst4[i];
            int4 r = rel4[i];
            float e0 = __expf(g_s_src[s.x] + g_s_rel[r.x] + g_s_tgt[d.x] + ab);
            float e1 = __expf(g_s_src[s.y] + g_s_rel[r.y] + g_s_tgt[d.y] + ab);
            float e2 = __expf(g_s_src[s.z] + g_s_rel[r.z] + g_s_tgt[d.z] + ab);
            float e3 = __expf(g_s_src[s.w] + g_s_rel[r.w] + g_s_tgt[d.w] + ab);
            int p0 = atomicAdd(&g_cursor[d.x], 1);
            int p1 = atomicAdd(&g_cursor[d.y], 1);
            int p2 = atomicAdd(&g_cursor[d.z], 1);
            int p3 = atomicAdd(&g_cursor[d.w], 1);
            g_epack[p0] = make_uint2((unsigned)s.x | ((unsigned)r.x << 16), __float_as_uint(e0));
            g_epack[p1] = make_uint2((unsigned)s.y | ((unsigned)r.y << 16), __float_as_uint(e1));
            g_epack[p2] = make_uint2((unsigned)s.z | ((unsigned)r.z << 16), __float_as_uint(e2));
            g_epack[p3] = make_uint2((unsigned)s.w | ((unsigned)r.w << 16), __float_as_uint(e3));
        }
    }

    grid_barrier(nblocks);

    // ---- Phase C: warp-per-node aggregate (proven R8 form) ----
    {
        int warp = tid >> 5, lane = tid & 31;
        for (int n = blk * 8 + warp; n < N_NODES; n += nblocks * 8) {
            int beg = g_offset[n], end = g_offset[n + 1];
            float4 res;
            if (end > beg) {
                float4 acc = make_float4(0.f, 0.f, 0.f, 0.f);
                float denom = 0.f;
                for (int e = beg; e < end; e++) {
                    uint2 pe = g_epack[e];
                    float ex = __uint_as_float(pe.y);
                    int s = pe.x & 0xFFFF;
                    int r = pe.x >> 16;
                    float4 mv = ((const float4*)g_m_node)[s * (DIM / 4) + lane];
                    float4 rv = ((const float4*)g_m_rel)[r * (DIM / 4) + lane];
                    acc.x += ex * (mv.x + rv.x);
                    acc.y += ex * (mv.y + rv.y);
                    acc.z += ex * (mv.z + rv.z);
                    acc.w += ex * (mv.w + rv.w);
                    denom += ex;
                }
                float inv = 1.f / denom;
                res = make_float4(acc.x * inv, acc.y * inv, acc.z * inv, acc.w * inv);
            } else {
                res = ((const float4*)node_emb)[n * (DIM / 4) + lane];
            }
            ((float4*)out)[n * (DIM / 4) + lane] = res;
        }
    }
}

// ---------------------------------------------------------------------------
extern "C" void kernel_launch(void* const* d_in, const int* in_sizes, int n_in,
                              void* d_out, int out_size) {
    const float* node_emb = (const float*)d_in[0];
    const float* rel_emb  = (const float*)d_in[1];
    const float* Wn       = (const float*)d_in[2];
    const float* bn       = (const float*)d_in[3];
    const float* Wr       = (const float*)d_in[4];
    const float* br       = (const float*)d_in[5];
    const float* attn_w   = (const float*)d_in[6];
    const float* attn_b   = (const float*)d_in[7];
    const int*   src      = (const int*)d_in[8];
    const int*   dst      = (const int*)d_in[9];
    const int*   rel      = (const int*)d_in[10];
    float* out = (float*)d_out;

    const int SMEM = (DIM * 132 + 64 * DIM + 2 * DIM) * (int)sizeof(float);  // 101,376 B
    cudaFuncSetAttribute(k_precomp, cudaFuncAttributeMaxDynamicSharedMemorySize, SMEM);

    // size the persistent grid for guaranteed co-residency
    int dev = 0, sms = 148, occ = 4;
    cudaGetDevice(&dev);
    cudaDeviceGetAttribute(&sms, cudaDevAttrMultiProcessorCount, dev);
    cudaOccupancyMaxActiveBlocksPerMultiprocessor(&occ, k_fused, 256, 0);
    if (occ > 4) occ = 4;
    if (occ < 1) occ = 1;
    unsigned nblocks = (unsigned)(sms * occ);
    if (nblocks < SCAN_CHUNKS) nblocks = SCAN_CHUNKS;   // scan needs 196 blocks

    k_precomp<<<NODE_BLOCKS + REL_BLOCKS, 256, SMEM>>>(node_emb, rel_emb, Wn, bn,
                                                       Wr, br, attn_w,
                                                       (const int4*)dst);
    k_fused<<<nblocks, 256>>>((const int4*)src, (const int4*)dst, (const int4*)rel,
                              attn_b, node_emb, out, nblocks);
}

// round 13
// speedup vs baseline: 1.1929x; 1.1929x over previous
#include <cuda_runtime.h>
#include <math.h>

#define N_NODES 50000
#define N_EDGES 600000
#define N_RELS  500
#define DIM     128
#define NODE_BLOCKS ((N_NODES + 63) / 64)   // 782
#define REL_BLOCKS  ((N_RELS + 63) / 64)    // 8
#define SCAN_CHUNKS ((N_NODES + 255) / 256)   // 196
#define SCAN_FLAG   (1ull << 63)
#define PAD 132   // smem row pitch in floats (bank-conflict-free fragments)

// ---- scratch (no allocations allowed) ----
__device__ __align__(16) float g_m_node[N_NODES * DIM];
__device__ __align__(16) float g_m_rel[N_RELS * DIM];
__device__ float g_s_src[N_NODES];
__device__ float g_s_tgt[N_NODES];
__device__ float g_s_rel[N_RELS];
__device__ float g_dummy[N_RELS];
__device__ int   g_count[N_NODES];       // zero-init; re-zeroed by k_scan each run
__device__ int   g_offset[N_NODES + 1];
__device__ int   g_cursor[N_NODES];
__device__ unsigned long long g_scan_ll[SCAN_CHUNKS];  // aggregate | FLAG; reset by k_precomp
__device__ __align__(8) uint2 g_epack[N_EDGES];   // {src | rel<<16, exp(score) bits}

// ---------------------------------------------------------------------------
__device__ __forceinline__ unsigned cvt_tf32(float f) {
    unsigned u;
    asm("cvt.rna.tf32.f32 %0, %1;" : "=r"(u) : "f"(f));
    return u;
}
__device__ __forceinline__ void mma_tf32(float* c, unsigned a0, unsigned a1,
                                         unsigned a2, unsigned a3,
                                         unsigned b0, unsigned b1) {
    asm volatile(
        "mma.sync.aligned.m16n8k8.row.col.f32.tf32.tf32.f32 "
        "{%0,%1,%2,%3}, {%4,%5,%6,%7}, {%8,%9}, {%0,%1,%2,%3};\n"
        : "+f"(c[0]), "+f"(c[1]), "+f"(c[2]), "+f"(c[3])
        : "r"(a0), "r"(a1), "r"(a2), "r"(a3), "r"(b0), "r"(b1));
}

// ---------------------------------------------------------------------------
// Merged row transform (nodes + rels) via tf32 tensor-core MMA.
// Block = 64 rows x 128 cols. 8 warps: warp w -> rows (w/2)*16, col-half (w%2)*64.
// m = X @ W^T + b (tf32 mma, fp32 accum); s1 = x.v1, s2 = x.v2 (exact fp32).
// dst histogram fused; block 0 resets scan flags.
__global__ void k_precomp(const float* __restrict__ Xn, const float* __restrict__ Xr,
                          const float* __restrict__ Wn, const float* __restrict__ bn,
                          const float* __restrict__ Wr, const float* __restrict__ br,
                          const float* __restrict__ attn_w,
                          const int4* __restrict__ dst4) {
    extern __shared__ float sm[];
    float* Ws  = sm;                      // 128*PAD  (W row-major, tf32-rounded)
    float* xs  = Ws + DIM * PAD;          // 64*PAD   (X tile, exact fp32)
    float* sv1 = xs + 64 * PAD;           // 128
    float* sv2 = sv1 + DIM;               // 128

    int tid = threadIdx.x;
    int blk = blockIdx.x;
    int mode = (blk >= NODE_BLOCKS);

    if (blk == 0 && tid < SCAN_CHUNKS) g_scan_ll[tid] = 0ull;   // reset lookback flags

    const float* X  = mode ? Xr : Xn;
    const float* W  = mode ? Wr : Wn;
    const float* b  = mode ? br : bn;
    const float* v1 = mode ? attn_w + 2 * DIM : attn_w;
    const float* v2 = mode ? attn_w + 2 * DIM : attn_w + DIM;
    float* out_m  = mode ? g_m_rel : g_m_node;
    float* out_s1 = mode ? g_s_rel : g_s_src;
    float* out_s2 = mode ? g_dummy : g_s_tgt;
    int n_rows    = mode ? N_RELS  : N_NODES;
    int base      = (mode ? (blk - NODE_BLOCKS) : blk) * 64;

    // fused histogram (fire-and-forget atomics)
    for (int i = blk * blockDim.x + tid; i < N_EDGES / 4; i += gridDim.x * blockDim.x) {
        int4 d = dst4[i];
        atomicAdd(&g_count[d.x], 1);
        atomicAdd(&g_count[d.y], 1);
        atomicAdd(&g_count[d.z], 1);
        atomicAdd(&g_count[d.w], 1);
    }

    // stage W row-major, pre-rounded to tf32 (RNA, unbiased)
    for (int idx = tid; idx < DIM * DIM; idx += blockDim.x) {
        int j = idx >> 7, k = idx & 127;
        Ws[j * PAD + k] = __uint_as_float(cvt_tf32(W[idx]));
    }
    for (int k = tid; k < DIM; k += blockDim.x) { sv1[k] = v1[k]; sv2[k] = v2[k]; }

    // stage X tile (exact fp32), zero-padded rows
    for (int idx = tid; idx < 64 * (DIM / 4); idx += blockDim.x) {
        int n = idx >> 5, c = idx & 31;
        int row = base + n;
        float4 v = make_float4(0.f, 0.f, 0.f, 0.f);
        if (row < n_rows) v = ((const float4*)X)[row * (DIM / 4) + c];
        ((float4*)(xs))[n * (PAD / 4) + c] = v;
    }
    __syncthreads();

    int warp = tid >> 5, lane = tid & 31;
    int g = lane >> 2, tig = lane & 3;
    int rtile = warp >> 1;           // 0..3 -> rows rtile*16
    int chalf = warp & 1;            // 0..1 -> cols chalf*64
    int r0 = rtile * 16;

    float c[8][4];
#pragma unroll
    for (int nt = 0; nt < 8; nt++)
#pragma unroll
        for (int q = 0; q < 4; q++) c[nt][q] = 0.f;

#pragma unroll 4
    for (int kt = 0; kt < 16; kt++) {
        int kb = kt * 8;
        unsigned a0 = cvt_tf32(xs[(r0 + g)     * PAD + kb + tig]);
        unsigned a1 = cvt_tf32(xs[(r0 + g + 8) * PAD + kb + tig]);
        unsigned a2 = cvt_tf32(xs[(r0 + g)     * PAD + kb + 4 + tig]);
        unsigned a3 = cvt_tf32(xs[(r0 + g + 8) * PAD + kb + 4 + tig]);
#pragma unroll
        for (int nt = 0; nt < 8; nt++) {
            int col = chalf * 64 + nt * 8 + g;
            unsigned b0 = __float_as_uint(Ws[col * PAD + kb + tig]);
            unsigned b1 = __float_as_uint(Ws[col * PAD + kb + 4 + tig]);
            mma_tf32(c[nt], a0, a1, a2, a3, b0, b1);
        }
    }

    // epilogue: add bias, store (float2 per fragment row)
#pragma unroll
    for (int nt = 0; nt < 8; nt++) {
        int colb = chalf * 64 + nt * 8;
        float2 bv = ((const float2*)(b + colb))[tig];
        int row0 = base + r0 + g;
        int row1 = row0 + 8;
        if (row0 < n_rows)
            ((float2*)(out_m + row0 * DIM + colb))[tig] =
                make_float2(c[nt][0] + bv.x, c[nt][1] + bv.y);
        if (row1 < n_rows)
            ((float2*)(out_m + row1 * DIM + colb))[tig] =
                make_float2(c[nt][2] + bv.x, c[nt][3] + bv.y);
    }

    // s1/s2 dot products from the exact fp32 tile: warp w -> rows w*8 .. w*8+7
    for (int i = 0; i < 8; i++) {
        int n = warp * 8 + i;
        int row = base + n;
        if (row >= n_rows) break;
        const float* xr = xs + n * PAD;
        float p1 = 0.f, p2 = 0.f;
#pragma unroll
        for (int q = 0; q < 4; q++) {
            int k = lane * 4 + q;
            float xv = xr[k];
            p1 += xv * sv1[k];
            p2 += xv * sv2[k];
        }
#pragma unroll
        for (int o2 = 16; o2; o2 >>= 1) {
            p1 += __shfl_down_sync(0xffffffffu, p1, o2);
            p2 += __shfl_down_sync(0xffffffffu, p2, o2);
        }
        if (lane == 0) { out_s1[row] = p1; out_s2[row] = p2; }
    }
}

// ---------------------------------------------------------------------------
// Single-kernel decoupled-lookback exclusive scan (R11-proven).
__global__ void k_scan() {
    __shared__ int s[256];
    __shared__ int s_carry;
    int tid = threadIdx.x;
    int b   = blockIdx.x;
    int idx = b * 256 + tid;

    int v = (idx < N_NODES) ? g_count[idx] : 0;
    s[tid] = v;
    __syncthreads();
#pragma unroll
    for (int off = 1; off < 256; off <<= 1) {
        int t = (tid >= off) ? s[tid - off] : 0;
        __syncthreads();
        s[tid] += t;
        __syncthreads();
    }
    int incl = s[tid];

    if (tid == 255)
        atomicExch(&g_scan_ll[b], (unsigned long long)(unsigned)s[255] | SCAN_FLAG);

    if (tid < 32) {
        int running = 0;
        int pos = b - 1 - tid;
        while (__any_sync(0xffffffffu, pos >= 0)) {
            if (pos >= 0) {
                unsigned long long got;
                do { got = atomicAdd(&g_scan_ll[pos], 0ull); } while (!(got & SCAN_FLAG));
                running += (int)(unsigned)(got & 0xFFFFFFFFull);
            }
            pos -= 32;
        }
#pragma unroll
        for (int o = 16; o; o >>= 1) running += __shfl_xor_sync(0xffffffffu, running, o);
        if (tid == 0) s_carry = running;
    }
    __syncthreads();
    int carry = s_carry;

    if (idx < N_NODES) {
        int o = carry + incl - v;
        g_offset[idx] = o;
        g_cursor[idx] = o;
        g_count[idx]  = 0;
    }
    if (idx == 0) g_offset[N_NODES] = N_EDGES;
}

// ---------------------------------------------------------------------------
// Fill CSR with (pack, exp(score)) — exp computed here, off agg's critical path.
__global__ void k_fill(const int4* __restrict__ src4, const int4* __restrict__ dst4,
                       const int4* __restrict__ rel4, const float* __restrict__ attn_b) {
    int i = blockIdx.x * blockDim.x + threadIdx.x;
    if (i >= N_EDGES / 4) return;
    int4 s = src4[i];
    int4 d = dst4[i];
    int4 r = rel4[i];
    float ab = attn_b[0];

    float e0 = __expf(g_s_src[s.x] + g_s_rel[r.x] + g_s_tgt[d.x] + ab);
    float e1 = __expf(g_s_src[s.y] + g_s_rel[r.y] + g_s_tgt[d.y] + ab);
    float e2 = __expf(g_s_src[s.z] + g_s_rel[r.z] + g_s_tgt[d.z] + ab);
    float e3 = __expf(g_s_src[s.w] + g_s_rel[r.w] + g_s_tgt[d.w] + ab);

    int p0 = atomicAdd(&g_cursor[d.x], 1);
    int p1 = atomicAdd(&g_cursor[d.y], 1);
    int p2 = atomicAdd(&g_cursor[d.z], 1);
    int p3 = atomicAdd(&g_cursor[d.w], 1);
    g_epack[p0] = make_uint2((unsigned)s.x | ((unsigned)r.x << 16), __float_as_uint(e0));
    g_epack[p1] = make_uint2((unsigned)s.y | ((unsigned)r.y << 16), __float_as_uint(e1));
    g_epack[p2] = make_uint2((unsigned)s.z | ((unsigned)r.z << 16), __float_as_uint(e2));
    g_epack[p3] = make_uint2((unsigned)s.w | ((unsigned)r.w << 16), __float_as_uint(e3));
}

// ---------------------------------------------------------------------------
// One warp per dst node: weighted aggregate with precomputed exp (R8-proven).
__global__ void k_node_agg(const float* __restrict__ node_emb,
                           float* __restrict__ out) {
    int gid = blockIdx.x * blockDim.x + threadIdx.x;
    int n = gid >> 5;
    if (n >= N_NODES) return;
    int lane = gid & 31;
    int beg = g_offset[n], end = g_offset[n + 1];
    float4 res;
    if (end > beg) {
        float4 acc = make_float4(0.f, 0.f, 0.f, 0.f);
        float denom = 0.f;
        for (int e = beg; e < end; e++) {
            uint2 pe = g_epack[e];
            float ex = __uint_as_float(pe.y);
            int s = pe.x & 0xFFFF;
            int r = pe.x >> 16;
            float4 mv = ((const float4*)g_m_node)[s * (DIM / 4) + lane];
            float4 rv = ((const float4*)g_m_rel)[r * (DIM / 4) + lane];
            acc.x += ex * (mv.x + rv.x);
            acc.y += ex * (mv.y + rv.y);
            acc.z += ex * (mv.z + rv.z);
            acc.w += ex * (mv.w + rv.w);
            denom += ex;
        }
        float inv = 1.f / denom;
        res = make_float4(acc.x * inv, acc.y * inv, acc.z * inv, acc.w * inv);
    } else {
        res = ((const float4*)node_emb)[n * (DIM / 4) + lane];
    }
    ((float4*)out)[n * (DIM / 4) + lane] = res;
}

// ---------------------------------------------------------------------------
extern "C" void kernel_launch(void* const* d_in, const int* in_sizes, int n_in,
                              void* d_out, int out_size) {
    const float* node_emb = (const float*)d_in[0];
    const float* rel_emb  = (const float*)d_in[1];
    const float* Wn       = (const float*)d_in[2];
    const float* bn       = (const float*)d_in[3];
    const float* Wr       = (const float*)d_in[4];
    const float* br       = (const float*)d_in[5];
    const float* attn_w   = (const float*)d_in[6];
    const float* attn_b   = (const float*)d_in[7];
    const int*   src      = (const int*)d_in[8];
    const int*   dst      = (const int*)d_in[9];
    const int*   rel      = (const int*)d_in[10];
    float* out = (float*)d_out;

    const int SMEM = (DIM * PAD + 64 * PAD + 2 * DIM) * (int)sizeof(float);  // 102,400 B
    cudaFuncSetAttribute(k_precomp, cudaFuncAttributeMaxDynamicSharedMemorySize, SMEM);

    int eb4 = (N_EDGES / 4 + 255) / 256;

    k_precomp<<<NODE_BLOCKS + REL_BLOCKS, 256, SMEM>>>(node_emb, rel_emb, Wn, bn,
                                                       Wr, br, attn_w,
                                                       (const int4*)dst);
    k_scan<<<SCAN_CHUNKS, 256>>>();
    k_fill<<<eb4, 256>>>((const int4*)src, (const int4*)dst, (const int4*)rel, attn_b);
    k_node_agg<<<(N_NODES * 32 + 255) / 256, 256>>>(node_emb, out);
}

// round 14
// speedup vs baseline: 1.2237x; 1.0258x over previous
#include <cuda_runtime.h>
#include <cuda_fp16.h>
#include <math.h>

#define N_NODES 50000
#define N_EDGES 600000
#define N_RELS  500
#define DIM     128
#define NODE_BLOCKS ((N_NODES + 63) / 64)   // 782
#define REL_BLOCKS  ((N_RELS + 63) / 64)    // 8
#define SCAN_CHUNKS ((N_NODES + 255) / 256)   // 196
#define SCAN_FLAG   (1ull << 63)
#define PAD 132   // smem row pitch in floats (bank-conflict-free fragments)

// ---- scratch (no allocations allowed) ----
__device__ __align__(16) __half g_m_node[N_NODES * DIM];   // fp16 messages
__device__ __align__(16) __half g_m_rel[N_RELS * DIM];
__device__ float g_s_src[N_NODES];
__device__ float g_s_tgt[N_NODES];
__device__ float g_s_rel[N_RELS];
__device__ float g_dummy[N_RELS];
__device__ int   g_count[N_NODES];       // zero-init; re-zeroed by k_scan each run
__device__ int   g_offset[N_NODES + 1];
__device__ int   g_cursor[N_NODES];
__device__ unsigned long long g_scan_ll[SCAN_CHUNKS];  // aggregate | FLAG; reset by k_precomp
__device__ __align__(8) uint2 g_epack[N_EDGES];   // {src | rel<<16, exp(score) bits}

// ---------------------------------------------------------------------------
__device__ __forceinline__ unsigned cvt_tf32(float f) {
    unsigned u;
    asm("cvt.rna.tf32.f32 %0, %1;" : "=r"(u) : "f"(f));
    return u;
}
__device__ __forceinline__ void mma_tf32(float* c, unsigned a0, unsigned a1,
                                         unsigned a2, unsigned a3,
                                         unsigned b0, unsigned b1) {
    asm volatile(
        "mma.sync.aligned.m16n8k8.row.col.f32.tf32.tf32.f32 "
        "{%0,%1,%2,%3}, {%4,%5,%6,%7}, {%8,%9}, {%0,%1,%2,%3};\n"
        : "+f"(c[0]), "+f"(c[1]), "+f"(c[2]), "+f"(c[3])
        : "r"(a0), "r"(a1), "r"(a2), "r"(a3), "r"(b0), "r"(b1));
}

// ---------------------------------------------------------------------------
// Merged row transform (nodes + rels) via tf32 tensor-core MMA, fp16 output.
// Block = 64 rows x 128 cols. 8 warps: warp w -> rows (w/2)*16, col-half (w%2)*64.
// m = fp16(X @ W^T + b); s1 = x.v1, s2 = x.v2 (exact fp32).
// dst histogram fused; block 0 resets scan flags.
__global__ void k_precomp(const float* __restrict__ Xn, const float* __restrict__ Xr,
                          const float* __restrict__ Wn, const float* __restrict__ bn,
                          const float* __restrict__ Wr, const float* __restrict__ br,
                          const float* __restrict__ attn_w,
                          const int4* __restrict__ dst4) {
    extern __shared__ float sm[];
    float* Ws  = sm;                      // 128*PAD  (W row-major, tf32-rounded)
    float* xs  = Ws + DIM * PAD;          // 64*PAD   (X tile, exact fp32)
    float* sv1 = xs + 64 * PAD;           // 128
    float* sv2 = sv1 + DIM;               // 128

    int tid = threadIdx.x;
    int blk = blockIdx.x;
    int mode = (blk >= NODE_BLOCKS);

    if (blk == 0 && tid < SCAN_CHUNKS) g_scan_ll[tid] = 0ull;   // reset lookback flags

    const float* X  = mode ? Xr : Xn;
    const float* W  = mode ? Wr : Wn;
    const float* b  = mode ? br : bn;
    const float* v1 = mode ? attn_w + 2 * DIM : attn_w;
    const float* v2 = mode ? attn_w + 2 * DIM : attn_w + DIM;
    __half* out_m = mode ? g_m_rel : g_m_node;
    float* out_s1 = mode ? g_s_rel : g_s_src;
    float* out_s2 = mode ? g_dummy : g_s_tgt;
    int n_rows    = mode ? N_RELS  : N_NODES;
    int base      = (mode ? (blk - NODE_BLOCKS) : blk) * 64;

    // fused histogram (fire-and-forget atomics)
    for (int i = blk * blockDim.x + tid; i < N_EDGES / 4; i += gridDim.x * blockDim.x) {
        int4 d = dst4[i];
        atomicAdd(&g_count[d.x], 1);
        atomicAdd(&g_count[d.y], 1);
        atomicAdd(&g_count[d.z], 1);
        atomicAdd(&g_count[d.w], 1);
    }

    // stage W row-major, pre-rounded to tf32 (RNA, unbiased)
    for (int idx = tid; idx < DIM * DIM; idx += blockDim.x) {
        int j = idx >> 7, k = idx & 127;
        Ws[j * PAD + k] = __uint_as_float(cvt_tf32(W[idx]));
    }
    for (int k = tid; k < DIM; k += blockDim.x) { sv1[k] = v1[k]; sv2[k] = v2[k]; }

    // stage X tile (exact fp32), zero-padded rows
    for (int idx = tid; idx < 64 * (DIM / 4); idx += blockDim.x) {
        int n = idx >> 5, c = idx & 31;
        int row = base + n;
        float4 v = make_float4(0.f, 0.f, 0.f, 0.f);
        if (row < n_rows) v = ((const float4*)X)[row * (DIM / 4) + c];
        ((float4*)(xs))[n * (PAD / 4) + c] = v;
    }
    __syncthreads();

    int warp = tid >> 5, lane = tid & 31;
    int g = lane >> 2, tig = lane & 3;
    int rtile = warp >> 1;           // 0..3 -> rows rtile*16
    int chalf = warp & 1;            // 0..1 -> cols chalf*64
    int r0 = rtile * 16;

    float c[8][4];
#pragma unroll
    for (int nt = 0; nt < 8; nt++)
#pragma unroll
        for (int q = 0; q < 4; q++) c[nt][q] = 0.f;

#pragma unroll 4
    for (int kt = 0; kt < 16; kt++) {
        int kb = kt * 8;
        unsigned a0 = cvt_tf32(xs[(r0 + g)     * PAD + kb + tig]);
        unsigned a1 = cvt_tf32(xs[(r0 + g + 8) * PAD + kb + tig]);
        unsigned a2 = cvt_tf32(xs[(r0 + g)     * PAD + kb + 4 + tig]);
        unsigned a3 = cvt_tf32(xs[(r0 + g + 8) * PAD + kb + 4 + tig]);
#pragma unroll
        for (int nt = 0; nt < 8; nt++) {
            int col = chalf * 64 + nt * 8 + g;
            unsigned b0 = __float_as_uint(Ws[col * PAD + kb + tig]);
            unsigned b1 = __float_as_uint(Ws[col * PAD + kb + 4 + tig]);
            mma_tf32(c[nt], a0, a1, a2, a3, b0, b1);
        }
    }

    // epilogue: add bias, convert to fp16, store half2 per fragment row
#pragma unroll
    for (int nt = 0; nt < 8; nt++) {
        int colb = chalf * 64 + nt * 8;
        float2 bv = ((const float2*)(b + colb))[tig];
        int row0 = base + r0 + g;
        int row1 = row0 + 8;
        if (row0 < n_rows)
            ((__half2*)(out_m + row0 * DIM + colb))[tig] =
                __floats2half2_rn(c[nt][0] + bv.x, c[nt][1] + bv.y);
        if (row1 < n_rows)
            ((__half2*)(out_m + row1 * DIM + colb))[tig] =
                __floats2half2_rn(c[nt][2] + bv.x, c[nt][3] + bv.y);
    }

    // s1/s2 dot products from the exact fp32 tile: warp w -> rows w*8 .. w*8+7
    for (int i = 0; i < 8; i++) {
        int n = warp * 8 + i;
        int row = base + n;
        if (row >= n_rows) break;
        const float* xr = xs + n * PAD;
        float p1 = 0.f, p2 = 0.f;
#pragma unroll
        for (int q = 0; q < 4; q++) {
            int k = lane * 4 + q;
            float xv = xr[k];
            p1 += xv * sv1[k];
            p2 += xv * sv2[k];
        }
#pragma unroll
        for (int o2 = 16; o2; o2 >>= 1) {
            p1 += __shfl_down_sync(0xffffffffu, p1, o2);
            p2 += __shfl_down_sync(0xffffffffu, p2, o2);
        }
        if (lane == 0) { out_s1[row] = p1; out_s2[row] = p2; }
    }
}

// ---------------------------------------------------------------------------
// Single-kernel decoupled-lookback exclusive scan (R11-proven).
__global__ void k_scan() {
    __shared__ int s[256];
    __shared__ int s_carry;
    int tid = threadIdx.x;
    int b   = blockIdx.x;
    int idx = b * 256 + tid;

    int v = (idx < N_NODES) ? g_count[idx] : 0;
    s[tid] = v;
    __syncthreads();
#pragma unroll
    for (int off = 1; off < 256; off <<= 1) {
        int t = (tid >= off) ? s[tid - off] : 0;
        __syncthreads();
        s[tid] += t;
        __syncthreads();
    }
    int incl = s[tid];

    if (tid == 255)
        atomicExch(&g_scan_ll[b], (unsigned long long)(unsigned)s[255] | SCAN_FLAG);

    if (tid < 32) {
        int running = 0;
        int pos = b - 1 - tid;
        while (__any_sync(0xffffffffu, pos >= 0)) {
            if (pos >= 0) {
                unsigned long long got;
                do { got = atomicAdd(&g_scan_ll[pos], 0ull); } while (!(got & SCAN_FLAG));
                running += (int)(unsigned)(got & 0xFFFFFFFFull);
            }
            pos -= 32;
        }
#pragma unroll
        for (int o = 16; o; o >>= 1) running += __shfl_xor_sync(0xffffffffu, running, o);
        if (tid == 0) s_carry = running;
    }
    __syncthreads();
    int carry = s_carry;

    if (idx < N_NODES) {
        int o = carry + incl - v;
        g_offset[idx] = o;
        g_cursor[idx] = o;
        g_count[idx]  = 0;
    }
    if (idx == 0) g_offset[N_NODES] = N_EDGES;
}

// ---------------------------------------------------------------------------
// Fill CSR with (pack, exp(score)) — exp computed here, off agg's critical path.
__global__ void k_fill(const int4* __restrict__ src4, const int4* __restrict__ dst4,
                       const int4* __restrict__ rel4, const float* __restrict__ attn_b) {
    int i = blockIdx.x * blockDim.x + threadIdx.x;
    if (i >= N_EDGES / 4) return;
    int4 s = src4[i];
    int4 d = dst4[i];
    int4 r = rel4[i];
    float ab = attn_b[0];

    float e0 = __expf(g_s_src[s.x] + g_s_rel[r.x] + g_s_tgt[d.x] + ab);
    float e1 = __expf(g_s_src[s.y] + g_s_rel[r.y] + g_s_tgt[d.y] + ab);
    float e2 = __expf(g_s_src[s.z] + g_s_rel[r.z] + g_s_tgt[d.z] + ab);
    float e3 = __expf(g_s_src[s.w] + g_s_rel[r.w] + g_s_tgt[d.w] + ab);

    int p0 = atomicAdd(&g_cursor[d.x], 1);
    int p1 = atomicAdd(&g_cursor[d.y], 1);
    int p2 = atomicAdd(&g_cursor[d.z], 1);
    int p3 = atomicAdd(&g_cursor[d.w], 1);
    g_epack[p0] = make_uint2((unsigned)s.x | ((unsigned)r.x << 16), __float_as_uint(e0));
    g_epack[p1] = make_uint2((unsigned)s.y | ((unsigned)r.y << 16), __float_as_uint(e1));
    g_epack[p2] = make_uint2((unsigned)s.z | ((unsigned)r.z << 16), __float_as_uint(e2));
    g_epack[p3] = make_uint2((unsigned)s.w | ((unsigned)r.w << 16), __float_as_uint(e3));
}

// ---------------------------------------------------------------------------
// One warp per dst node: weighted aggregate, fp16 gathers, fp32 accumulation.
__global__ void k_node_agg(const float* __restrict__ node_emb,
                           float* __restrict__ out) {
    int gid = blockIdx.x * blockDim.x + threadIdx.x;
    int n = gid >> 5;
    if (n >= N_NODES) return;
    int lane = gid & 31;
    int beg = g_offset[n], end = g_offset[n + 1];
    float4 res;
    if (end > beg) {
        const uint2* mn2 = (const uint2*)g_m_node;   // row = 32 uint2 (4 halves each)
        const uint2* mr2 = (const uint2*)g_m_rel;
        float4 acc = make_float4(0.f, 0.f, 0.f, 0.f);
        float denom = 0.f;
        for (int e = beg; e < end; e++) {
            uint2 pe = g_epack[e];
            float ex = __uint_as_float(pe.y);
            int s = pe.x & 0xFFFF;
            int r = pe.x >> 16;
            uint2 a  = mn2[s * 32 + lane];
            uint2 b2 = mr2[r * 32 + lane];
            float2 f0 = __half22float2(*(__half2*)&a.x);
            float2 f1 = __half22float2(*(__half2*)&a.y);
            float2 g0 = __half22float2(*(__half2*)&b2.x);
            float2 g1 = __half22float2(*(__half2*)&b2.y);
            acc.x += ex * (f0.x + g0.x);
            acc.y += ex * (f0.y + g0.y);
            acc.z += ex * (f1.x + g1.x);
            acc.w += ex * (f1.y + g1.y);
            denom += ex;
        }
        float inv = 1.f / denom;
        res = make_float4(acc.x * inv, acc.y * inv, acc.z * inv, acc.w * inv);
    } else {
        res = ((const float4*)node_emb)[n * (DIM / 4) + lane];
    }
    ((float4*)out)[n * (DIM / 4) + lane] = res;
}

// ---------------------------------------------------------------------------
extern "C" void kernel_launch(void* const* d_in, const int* in_sizes, int n_in,
                              void* d_out, int out_size) {
    const float* node_emb = (const float*)d_in[0];
    const float* rel_emb  = (const float*)d_in[1];
    const float* Wn       = (const float*)d_in[2];
    const float* bn       = (const float*)d_in[3];
    const float* Wr       = (const float*)d_in[4];
    const float* br       = (const float*)d_in[5];
    const float* attn_w   = (const float*)d_in[6];
    const float* attn_b   = (const float*)d_in[7];
    const int*   src      = (const int*)d_in[8];
    const int*   dst      = (const int*)d_in[9];
    const int*   rel      = (const int*)d_in[10];
    float* out = (float*)d_out;

    const int SMEM = (DIM * PAD + 64 * PAD + 2 * DIM) * (int)sizeof(float);  // 102,400 B
    cudaFuncSetAttribute(k_precomp, cudaFuncAttributeMaxDynamicSharedMemorySize, SMEM);

    int eb4 = (N_EDGES / 4 + 255) / 256;

    k_precomp<<<NODE_BLOCKS + REL_BLOCKS, 256, SMEM>>>(node_emb, rel_emb, Wn, bn,
                                                       Wr, br, attn_w,
                                                       (const int4*)dst);
    k_scan<<<SCAN_CHUNKS, 256>>>();
    k_fill<<<eb4, 256>>>((const int4*)src, (const int4*)dst, (const int4*)rel, attn_b);
    k_node_agg<<<(N_NODES * 32 + 255) / 256, 256>>>(node_emb, out);
}

// round 15
// speedup vs baseline: 1.3303x; 1.0871x over previous
#include <cuda_runtime.h>
#include <cuda_fp16.h>
#include <math.h>

#define N_NODES 50000
#define N_EDGES 600000
#define N_RELS  500
#define DIM     128
#define NODE_BLOCKS ((N_NODES + 63) / 64)   // 782
#define REL_BLOCKS  ((N_RELS + 63) / 64)    // 8
#define SCAN_CHUNKS ((N_NODES + 255) / 256)   // 196
#define SCAN_FLAG   (1ull << 63)
#define PAD 132   // smem row pitch in floats (bank-conflict-free fragments)

// ---- scratch (no allocations allowed) ----
__device__ __align__(16) __half g_m_node[N_NODES * DIM];   // fp16 messages
__device__ __align__(16) __half g_m_rel[N_RELS * DIM];
__device__ float g_s_src[N_NODES];
__device__ float g_s_tgt[N_NODES];
__device__ float g_s_rel[N_RELS];
__device__ float g_dummy[N_RELS];
__device__ int   g_count[N_NODES];       // zero-init; re-zeroed by k_scan each run
__device__ int   g_offset[N_NODES + 1];
__device__ int   g_cursor[N_NODES];
__device__ unsigned long long g_scan_ll[SCAN_CHUNKS];  // aggregate | FLAG; reset by k_precomp
__device__ __align__(8) uint2 g_epack[N_EDGES];   // {src | rel<<16, exp(score) bits}

// ---------------------------------------------------------------------------
__device__ __forceinline__ unsigned cvt_tf32(float f) {
    unsigned u;
    asm("cvt.rna.tf32.f32 %0, %1;" : "=r"(u) : "f"(f));
    return u;
}
__device__ __forceinline__ void mma_tf32(float* c, unsigned a0, unsigned a1,
                                         unsigned a2, unsigned a3,
                                         unsigned b0, unsigned b1) {
    asm volatile(
        "mma.sync.aligned.m16n8k8.row.col.f32.tf32.tf32.f32 "
        "{%0,%1,%2,%3}, {%4,%5,%6,%7}, {%8,%9}, {%0,%1,%2,%3};\n"
        : "+f"(c[0]), "+f"(c[1]), "+f"(c[2]), "+f"(c[3])
        : "r"(a0), "r"(a1), "r"(a2), "r"(a3), "r"(b0), "r"(b1));
}

// ---------------------------------------------------------------------------
// Merged row transform (nodes + rels) via tf32 tensor-core MMA, fp16 output.
// Block = 64 rows x 128 cols. 8 warps: warp w -> rows (w/2)*16, col-half (w%2)*64.
// m = fp16(X @ W^T + b); s1 = x.v1, s2 = x.v2 (exact fp32).
// dst histogram fused; block 0 resets scan flags.
__global__ void k_precomp(const float* __restrict__ Xn, const float* __restrict__ Xr,
                          const float* __restrict__ Wn, const float* __restrict__ bn,
                          const float* __restrict__ Wr, const float* __restrict__ br,
                          const float* __restrict__ attn_w,
                          const int4* __restrict__ dst4) {
    extern __shared__ float sm[];
    float* Ws  = sm;                      // 128*PAD  (W row-major, tf32-rounded)
    float* xs  = Ws + DIM * PAD;          // 64*PAD   (X tile, exact fp32)
    float* sv1 = xs + 64 * PAD;           // 128
    float* sv2 = sv1 + DIM;               // 128

    int tid = threadIdx.x;
    int blk = blockIdx.x;
    int mode = (blk >= NODE_BLOCKS);

    if (blk == 0 && tid < SCAN_CHUNKS) g_scan_ll[tid] = 0ull;   // reset lookback flags

    const float* X  = mode ? Xr : Xn;
    const float* W  = mode ? Wr : Wn;
    const float* b  = mode ? br : bn;
    const float* v1 = mode ? attn_w + 2 * DIM : attn_w;
    const float* v2 = mode ? attn_w + 2 * DIM : attn_w + DIM;
    __half* out_m = mode ? g_m_rel : g_m_node;
    float* out_s1 = mode ? g_s_rel : g_s_src;
    float* out_s2 = mode ? g_dummy : g_s_tgt;
    int n_rows    = mode ? N_RELS  : N_NODES;
    int base      = (mode ? (blk - NODE_BLOCKS) : blk) * 64;

    // fused histogram (fire-and-forget atomics)
    for (int i = blk * blockDim.x + tid; i < N_EDGES / 4; i += gridDim.x * blockDim.x) {
        int4 d = dst4[i];
        atomicAdd(&g_count[d.x], 1);
        atomicAdd(&g_count[d.y], 1);
        atomicAdd(&g_count[d.z], 1);
        atomicAdd(&g_count[d.w], 1);
    }

    // stage W row-major, pre-rounded to tf32 (RNA, unbiased)
    for (int idx = tid; idx < DIM * DIM; idx += blockDim.x) {
        int j = idx >> 7, k = idx & 127;
        Ws[j * PAD + k] = __uint_as_float(cvt_tf32(W[idx]));
    }
    for (int k = tid; k < DIM; k += blockDim.x) { sv1[k] = v1[k]; sv2[k] = v2[k]; }

    // stage X tile (exact fp32), zero-padded rows
    for (int idx = tid; idx < 64 * (DIM / 4); idx += blockDim.x) {
        int n = idx >> 5, c = idx & 31;
        int row = base + n;
        float4 v = make_float4(0.f, 0.f, 0.f, 0.f);
        if (row < n_rows) v = ((const float4*)X)[row * (DIM / 4) + c];
        ((float4*)(xs))[n * (PAD / 4) + c] = v;
    }
    __syncthreads();

    int warp = tid >> 5, lane = tid & 31;
    int g = lane >> 2, tig = lane & 3;
    int rtile = warp >> 1;           // 0..3 -> rows rtile*16
    int chalf = warp & 1;            // 0..1 -> cols chalf*64
    int r0 = rtile * 16;

    float c[8][4];
#pragma unroll
    for (int nt = 0; nt < 8; nt++)
#pragma unroll
        for (int q = 0; q < 4; q++) c[nt][q] = 0.f;

#pragma unroll 4
    for (int kt = 0; kt < 16; kt++) {
        int kb = kt * 8;
        unsigned a0 = cvt_tf32(xs[(r0 + g)     * PAD + kb + tig]);
        unsigned a1 = cvt_tf32(xs[(r0 + g + 8) * PAD + kb + tig]);
        unsigned a2 = cvt_tf32(xs[(r0 + g)     * PAD + kb + 4 + tig]);
        unsigned a3 = cvt_tf32(xs[(r0 + g + 8) * PAD + kb + 4 + tig]);
#pragma unroll
        for (int nt = 0; nt < 8; nt++) {
            int col = chalf * 64 + nt * 8 + g;
            unsigned b0 = __float_as_uint(Ws[col * PAD + kb + tig]);
            unsigned b1 = __float_as_uint(Ws[col * PAD + kb + 4 + tig]);
            mma_tf32(c[nt], a0, a1, a2, a3, b0, b1);
        }
    }

    // epilogue: add bias, convert to fp16, store half2 per fragment row
#pragma unroll
    for (int nt = 0; nt < 8; nt++) {
        int colb = chalf * 64 + nt * 8;
        float2 bv = ((const float2*)(b + colb))[tig];
        int row0 = base + r0 + g;
        int row1 = row0 + 8;
        if (row0 < n_rows)
            ((__half2*)(out_m + row0 * DIM + colb))[tig] =
                __floats2half2_rn(c[nt][0] + bv.x, c[nt][1] + bv.y);
        if (row1 < n_rows)
            ((__half2*)(out_m + row1 * DIM + colb))[tig] =
                __floats2half2_rn(c[nt][2] + bv.x, c[nt][3] + bv.y);
    }

    // s1/s2 dot products from the exact fp32 tile: warp w -> rows w*8 .. w*8+7
    for (int i = 0; i < 8; i++) {
        int n = warp * 8 + i;
        int row = base + n;
        if (row >= n_rows) break;
        const float* xr = xs + n * PAD;
        float p1 = 0.f, p2 = 0.f;
#pragma unroll
        for (int q = 0; q < 4; q++) {
            int k = lane * 4 + q;
            float xv = xr[k];
            p1 += xv * sv1[k];
            p2 += xv * sv2[k];
        }
#pragma unroll
        for (int o2 = 16; o2; o2 >>= 1) {
            p1 += __shfl_down_sync(0xffffffffu, p1, o2);
            p2 += __shfl_down_sync(0xffffffffu, p2, o2);
        }
        if (lane == 0) { out_s1[row] = p1; out_s2[row] = p2; }
    }
}

// ---------------------------------------------------------------------------
// Single-kernel decoupled-lookback exclusive scan (R11-proven).
__global__ void k_scan() {
    __shared__ int s[256];
    __shared__ int s_carry;
    int tid = threadIdx.x;
    int b   = blockIdx.x;
    int idx = b * 256 + tid;

    int v = (idx < N_NODES) ? g_count[idx] : 0;
    s[tid] = v;
    __syncthreads();
#pragma unroll
    for (int off = 1; off < 256; off <<= 1) {
        int t = (tid >= off) ? s[tid - off] : 0;
        __syncthreads();
        s[tid] += t;
        __syncthreads();
    }
    int incl = s[tid];

    if (tid == 255)
        atomicExch(&g_scan_ll[b], (unsigned long long)(unsigned)s[255] | SCAN_FLAG);

    if (tid < 32) {
        int running = 0;
        int pos = b - 1 - tid;
        while (__any_sync(0xffffffffu, pos >= 0)) {
            if (pos >= 0) {
                unsigned long long got;
                do { got = atomicAdd(&g_scan_ll[pos], 0ull); } while (!(got & SCAN_FLAG));
                running += (int)(unsigned)(got & 0xFFFFFFFFull);
            }
            pos -= 32;
        }
#pragma unroll
        for (int o = 16; o; o >>= 1) running += __shfl_xor_sync(0xffffffffu, running, o);
        if (tid == 0) s_carry = running;
    }
    __syncthreads();
    int carry = s_carry;

    if (idx < N_NODES) {
        int o = carry + incl - v;
        g_offset[idx] = o;
        g_cursor[idx] = o;
        g_count[idx]  = 0;
    }
    if (idx == 0) g_offset[N_NODES] = N_EDGES;
}

// ---------------------------------------------------------------------------
// Fill CSR with (pack, exp(score)) — exp computed here, off agg's critical path.
__global__ void k_fill(const int4* __restrict__ src4, const int4* __restrict__ dst4,
                       const int4* __restrict__ rel4, const float* __restrict__ attn_b) {
    int i = blockIdx.x * blockDim.x + threadIdx.x;
    if (i >= N_EDGES / 4) return;
    int4 s = src4[i];
    int4 d = dst4[i];
    int4 r = rel4[i];
    float ab = attn_b[0];

    float e0 = __expf(g_s_src[s.x] + g_s_rel[r.x] + g_s_tgt[d.x] + ab);
    float e1 = __expf(g_s_src[s.y] + g_s_rel[r.y] + g_s_tgt[d.y] + ab);
    float e2 = __expf(g_s_src[s.z] + g_s_rel[r.z] + g_s_tgt[d.z] + ab);
    float e3 = __expf(g_s_src[s.w] + g_s_rel[r.w] + g_s_tgt[d.w] + ab);

    int p0 = atomicAdd(&g_cursor[d.x], 1);
    int p1 = atomicAdd(&g_cursor[d.y], 1);
    int p2 = atomicAdd(&g_cursor[d.z], 1);
    int p3 = atomicAdd(&g_cursor[d.w], 1);
    g_epack[p0] = make_uint2((unsigned)s.x | ((unsigned)r.x << 16), __float_as_uint(e0));
    g_epack[p1] = make_uint2((unsigned)s.y | ((unsigned)r.y << 16), __float_as_uint(e1));
    g_epack[p2] = make_uint2((unsigned)s.z | ((unsigned)r.z << 16), __float_as_uint(e2));
    g_epack[p3] = make_uint2((unsigned)s.w | ((unsigned)r.w << 16), __float_as_uint(e3));
}

// ---------------------------------------------------------------------------
// One warp per dst node: weighted aggregate. fp16 gathers, half2 msg-sum,
// fp32 accumulation (4 cvt + 4 ffma + 2 hadd2 per edge).
__global__ void k_node_agg(const float* __restrict__ node_emb,
                           float* __restrict__ out) {
    int gid = blockIdx.x * blockDim.x + threadIdx.x;
    int n = gid >> 5;
    if (n >= N_NODES) return;
    int lane = gid & 31;
    int beg = g_offset[n], end = g_offset[n + 1];
    float4 res;
    if (end > beg) {
        const uint2* mn2 = (const uint2*)g_m_node;   // row = 32 uint2 (4 halves each)
        const uint2* mr2 = (const uint2*)g_m_rel;
        float4 acc = make_float4(0.f, 0.f, 0.f, 0.f);
        float denom = 0.f;
        for (int e = beg; e < end; e++) {
            uint2 pe = g_epack[e];
            float ex = __uint_as_float(pe.y);
            int s = pe.x & 0xFFFF;
            int r = pe.x >> 16;
            uint2 a  = mn2[s * 32 + lane];
            uint2 b2 = mr2[r * 32 + lane];
            __half2 s0 = __hadd2(*(__half2*)&a.x, *(__half2*)&b2.x);
            __half2 s1 = __hadd2(*(__half2*)&a.y, *(__half2*)&b2.y);
            float2 f0 = __half22float2(s0);
            float2 f1 = __half22float2(s1);
            acc.x += ex * f0.x;
            acc.y += ex * f0.y;
            acc.z += ex * f1.x;
            acc.w += ex * f1.y;
            denom += ex;
        }
        float inv = 1.f / denom;
        res = make_float4(acc.x * inv, acc.y * inv, acc.z * inv, acc.w * inv);
    } else {
        res = ((const float4*)node_emb)[n * (DIM / 4) + lane];
    }
    ((float4*)out)[n * (DIM / 4) + lane] = res;
}

// ---------------------------------------------------------------------------
extern "C" void kernel_launch(void* const* d_in, const int* in_sizes, int n_in,
                              void* d_out, int out_size) {
    const float* node_emb = (const float*)d_in[0];
    const float* rel_emb  = (const float*)d_in[1];
    const float* Wn       = (const float*)d_in[2];
    const float* bn       = (const float*)d_in[3];
    const float* Wr       = (const float*)d_in[4];
    const float* br       = (const float*)d_in[5];
    const float* attn_w   = (const float*)d_in[6];
    const float* attn_b   = (const float*)d_in[7];
    const int*   src      = (const int*)d_in[8];
    const int*   dst      = (const int*)d_in[9];
    const int*   rel      = (const int*)d_in[10];
    float* out = (float*)d_out;

    const int SMEM = (DIM * PAD + 64 * PAD + 2 * DIM) * (int)sizeof(float);  // 102,400 B
    cudaFuncSetAttribute(k_precomp, cudaFuncAttributeMaxDynamicSharedMemorySize, SMEM);

    int eb4 = (N_EDGES / 4 + 255) / 256;

    k_precomp<<<NODE_BLOCKS + REL_BLOCKS, 256, SMEM>>>(node_emb, rel_emb, Wn, bn,
                                                       Wr, br, attn_w,
                                                       (const int4*)dst);
    k_scan<<<SCAN_CHUNKS, 256>>>();
    k_fill<<<eb4, 256>>>((const int4*)src, (const int4*)dst, (const int4*)rel, attn_b);
    k_node_agg<<<(N_NODES * 32 + 255) / 256, 256>>>(node_emb, out);
}